// round 12
// baseline (speedup 1.0000x reference)
#include <cuda_runtime.h>
#include <cuda_fp16.h>
#include <math.h>
#include <stdint.h>

#define BN_EPS 1e-5f

// Problem constants
#define B_   2
#define C_   512
#define HW_  6400
#define CK_  256
#define CV_  256
#define CO_  512
#define NSPLIT 4
#define KSPLIT (HW_ / NSPLIT)   // 1600
#define NT_  50                 // 6400 / 128 tiles per dim

#define NSTAGE 4
#define KCH   32                          // k-halfs per chunk
#define SROW  40                          // halfs per smem row (32 + 8 pad)
#define STAGE_H (2 * 128 * SROW)          // halfs per stage (A+B)
#define SMEM_DYN (NSTAGE * STAGE_H * 2)   // 81920 bytes

// ---------------------------------------------------------------------------
// Scratch (device globals)
// ---------------------------------------------------------------------------
__device__ __align__(16) __half g_xt [(size_t)B_ * HW_ * C_];   // x^T: [b][n][c]
__device__ __align__(16) __half g_wr [3 * 131072];              // wk | wv | wW (half)
__device__ __align__(16) __half g_kt [(size_t)B_ * HW_ * CK_];  // K^T: [pixel][channel]
__device__ __align__(16) __half g_v  [(size_t)B_ * CV_ * HW_];  // V: [vchan][pixel]
__device__ __align__(16) __half g_sim[(size_t)B_ * HW_ * HW_];  // exp(S - u_row)
__device__ __align__(16) __half g_ctx[(size_t)B_ * HW_ * CV_];  // ctx^T: [n][v] normalized
__device__ float g_ctxp[(size_t)B_ * NSPLIT * HW_ * CV_];       // ctx partials (fp32)
__device__ float g_rn  [(size_t)B_ * HW_];                      // ||k_r||^2 (stored-half K)
__device__ unsigned g_gsq_bits[B_];                             // max ||k_r||^2 (as bits)
__device__ float g_ps  [(size_t)B_ * HW_ * NT_];                // row-sum partials
__device__ float g_inv [(size_t)B_ * HW_];                      // 1/rowsum

// ---------------------------------------------------------------------------
// Helpers
// ---------------------------------------------------------------------------
__device__ __forceinline__ void mma_f16(float* c, const uint32_t* a, const uint32_t* b) {
    asm volatile(
        "mma.sync.aligned.m16n8k16.row.col.f32.f16.f16.f32 "
        "{%0,%1,%2,%3}, {%4,%5,%6,%7}, {%8,%9}, {%0,%1,%2,%3};"
        : "+f"(c[0]), "+f"(c[1]), "+f"(c[2]), "+f"(c[3])
        : "r"(a[0]), "r"(a[1]), "r"(a[2]), "r"(a[3]), "r"(b[0]), "r"(b[1]));
}

__device__ __forceinline__ void ldm4(uint32_t& r0, uint32_t& r1, uint32_t& r2,
                                     uint32_t& r3, uint32_t addr) {
    asm volatile("ldmatrix.sync.aligned.m8n8.x4.shared.b16 {%0,%1,%2,%3}, [%4];"
                 : "=r"(r0), "=r"(r1), "=r"(r2), "=r"(r3) : "r"(addr));
}

__device__ __forceinline__ void cp16(uint32_t saddr, const void* g) {
    asm volatile("cp.async.cg.shared.global [%0], [%1], 16;" :: "r"(saddr), "l"(g));
}
__device__ __forceinline__ void cp_commit() {
    asm volatile("cp.async.commit_group;");
}
template<int N> __device__ __forceinline__ void cp_wait() {
    asm volatile("cp.async.wait_group %0;" :: "n"(N));
}

// ---------------------------------------------------------------------------
// Pipelined FP16 mainloop: acc += sum_{k in [kb,ke)} A[m][k]*B[n][k]
// 128x128 tile, 8 warps, 4-stage cp.async, ldmatrix fragment loads.
// ---------------------------------------------------------------------------
__device__ __forceinline__ void mma_mainloop_h(
    const __half* __restrict__ A, const __half* __restrict__ B,
    int lda, int ldb, int kb, int ke, float acc[2][8][4])
{
    extern __shared__ __half smh[];
    const int tid  = threadIdx.x;
    const int lane = tid & 31;
    const int wid  = tid >> 5;
    const int warpM0 = (wid & 3) * 32;
    const int warpN0 = (wid >> 2) * 64;

    const int lr   = tid >> 1;
    const int hseg = (tid & 1) * 16;

    const __half* Ar = A + (size_t)lr * lda + kb + hseg;
    const __half* Br = B + (size_t)lr * ldb + kb + hseg;

    const uint32_t sbase = (uint32_t)__cvta_generic_to_shared(smh);

    uint32_t a_off[2][2], b_off[2][4];
    {
        const int ra = warpM0 + (lane & 15);
        const int ca = (lane >> 4) * 8;
        #pragma unroll
        for (int i = 0; i < 2; i++)
            #pragma unroll
            for (int s = 0; s < 2; s++)
                a_off[i][s] = (uint32_t)(((ra + i * 16) * SROW + s * 16 + ca) * 2);
        const int jj = lane >> 4;
        const int cb = ((lane >> 3) & 1) * 8;
        #pragma unroll
        for (int jp = 0; jp < 4; jp++)
            #pragma unroll
            for (int s = 0; s < 2; s++)
                b_off[s][jp] = (uint32_t)((128 * SROW +
                    (warpN0 + (jp * 2 + jj) * 8 + (lane & 7)) * SROW + s * 16 + cb) * 2);
    }

    const int ktiles = (ke - kb) / KCH;

#define ISSUE_TILE(stage, kof) do {                                  \
        uint32_t so_ = sbase + (stage) * (STAGE_H * 2);              \
        uint32_t sa_ = so_ + (lr * SROW + hseg) * 2;                 \
        uint32_t sb_ = sa_ + 128 * SROW * 2;                         \
        cp16(sa_,      Ar + (kof));                                  \
        cp16(sa_ + 16, Ar + (kof) + 8);                              \
        cp16(sb_,      Br + (kof));                                  \
        cp16(sb_ + 16, Br + (kof) + 8);                              \
    } while (0)

    ISSUE_TILE(0, 0);       cp_commit();
    ISSUE_TILE(1, KCH);     cp_commit();
    ISSUE_TILE(2, 2 * KCH); cp_commit();

    for (int t = 0; t < ktiles; t++) {
        cp_wait<2>();
        __syncthreads();
        if (t + 3 < ktiles) ISSUE_TILE((t + 3) & 3, (t + 3) * KCH);
        cp_commit();

        const uint32_t so = sbase + (t & 3) * (STAGE_H * 2);
        #pragma unroll
        for (int s = 0; s < 2; s++) {
            uint32_t a[2][4], b[8][2];
            ldm4(a[0][0], a[0][1], a[0][2], a[0][3], so + a_off[0][s]);
            ldm4(a[1][0], a[1][1], a[1][2], a[1][3], so + a_off[1][s]);
            ldm4(b[0][0], b[0][1], b[1][0], b[1][1], so + b_off[s][0]);
            ldm4(b[2][0], b[2][1], b[3][0], b[3][1], so + b_off[s][1]);
            ldm4(b[4][0], b[4][1], b[5][0], b[5][1], so + b_off[s][2]);
            ldm4(b[6][0], b[6][1], b[7][0], b[7][1], so + b_off[s][3]);
            #pragma unroll
            for (int i = 0; i < 2; i++)
                #pragma unroll
                for (int j = 0; j < 8; j++)
                    mma_f16(acc[i][j], a[i], b[j]);
        }
    }
#undef ISSUE_TILE
}

// ---------------------------------------------------------------------------
// Transpose + halve x: [b][c][n] -> g_xt [b][n][c].  grid (200,16,2), 32x8
// ---------------------------------------------------------------------------
__global__ void __launch_bounds__(256) transpose_x(const float* __restrict__ x)
{
    __shared__ float t[32][33];
    const int n0 = blockIdx.x * 32;
    const int c0 = blockIdx.y * 32;
    const int b  = blockIdx.z;
    const int tx = threadIdx.x, ty = threadIdx.y;

    #pragma unroll
    for (int j = 0; j < 4; j++) {
        int c = c0 + ty + j * 8;
        t[ty + j * 8][tx] = x[((size_t)b * C_ + c) * HW_ + n0 + tx];
    }
    __syncthreads();
    #pragma unroll
    for (int j = 0; j < 4; j++) {
        int n = n0 + ty + j * 8;
        g_xt[((size_t)b * HW_ + n) * C_ + c0 + tx] = __float2half_rn(t[tx][ty + j * 8]);
    }
}

// Halve weight matrices.  grid (1536), 256 thr
__global__ void __launch_bounds__(256) round_w(
    const float* __restrict__ wk, const float* __restrict__ wv,
    const float* __restrict__ wW)
{
    const int i = blockIdx.x * 256 + threadIdx.x;
    const float* src = (i < 131072) ? (wk + i)
                     : (i < 262144) ? (wv + i - 131072)
                                    : (wW + i - 262144);
    g_wr[i] = __float2half_rn(*src);
}

// ---------------------------------------------------------------------------
// kv via mma.  grid (50, 2, 4)  z = b*2 + isV
// ---------------------------------------------------------------------------
__global__ void __launch_bounds__(256, 2) kv_mma(
    const float* __restrict__ bk,
    const float* __restrict__ gamma, const float* __restrict__ beta,
    const float* __restrict__ rmean, const float* __restrict__ rvar,
    const float* __restrict__ bv)
{
    const int n0 = blockIdx.x * 128;
    const int m0 = blockIdx.y * 128;
    const int b  = blockIdx.z >> 1;
    const int isV = blockIdx.z & 1;

    const __half* A = g_wr + (size_t)isV * 131072 + (size_t)m0 * C_;
    const __half* B = g_xt + ((size_t)b * HW_ + n0) * C_;

    float acc[2][8][4] = {};
    mma_mainloop_h(A, B, C_, C_, 0, C_, acc);

    const int lane = threadIdx.x & 31;
    const int wid  = threadIdx.x >> 5;
    const int warpM0 = (wid & 3) * 32;
    const int warpN0 = (wid >> 2) * 64;
    const int t4 = lane >> 2;
    const int tm = lane & 3;

    if (isV) {
        __half* V = g_v + (size_t)b * CV_ * HW_;
        #pragma unroll
        for (int i = 0; i < 2; i++) {
            int r1 = m0 + warpM0 + i * 16 + t4;
            int r2 = r1 + 8;
            float b1 = bv[r1], b2 = bv[r2];
            #pragma unroll
            for (int j = 0; j < 8; j++) {
                int cg = n0 + warpN0 + j * 8 + tm * 2;
                *(__half2*)&V[(size_t)r1 * HW_ + cg] =
                    __floats2half2_rn(acc[i][j][0] + b1, acc[i][j][1] + b1);
                *(__half2*)&V[(size_t)r2 * HW_ + cg] =
                    __floats2half2_rn(acc[i][j][2] + b2, acc[i][j][3] + b2);
            }
        }
    } else {
        __half* kt = g_kt + (size_t)b * HW_ * CK_;
        #pragma unroll
        for (int i = 0; i < 2; i++) {
            int r1 = m0 + warpM0 + i * 16 + t4;
            int r2 = r1 + 8;
            float bb1 = bk[r1], bb2 = bk[r2];
            float sc1 = gamma[r1] / sqrtf(rvar[r1] + BN_EPS);
            float sc2 = gamma[r2] / sqrtf(rvar[r2] + BN_EPS);
            float mu1 = rmean[r1], mu2 = rmean[r2];
            float be1 = beta[r1],  be2 = beta[r2];
            #pragma unroll
            for (int j = 0; j < 8; j++) {
                int cg = n0 + warpN0 + j * 8 + tm * 2;
                float t0 = fmaxf((acc[i][j][0] + bb1 - mu1) * sc1 + be1, 0.f);
                float t1 = fmaxf((acc[i][j][1] + bb1 - mu1) * sc1 + be1, 0.f);
                float t2 = fmaxf((acc[i][j][2] + bb2 - mu2) * sc2 + be2, 0.f);
                float t3 = fmaxf((acc[i][j][3] + bb2 - mu2) * sc2 + be2, 0.f);
                kt[(size_t)cg * CK_ + r1]       = __float2half_rn(t0);
                kt[(size_t)(cg + 1) * CK_ + r1] = __float2half_rn(t1);
                kt[(size_t)cg * CK_ + r2]       = __float2half_rn(t2);
                kt[(size_t)(cg + 1) * CK_ + r2] = __float2half_rn(t3);
            }
        }
    }
}

// ---------------------------------------------------------------------------
// Symmetric sim: fused exp + partial sums, mirror staged via smem.
// grid (1275, 1, 2), 256 threads.
// ---------------------------------------------------------------------------
__global__ void __launch_bounds__(256, 2) sim_sym()
{
    int rem = blockIdx.x, ti = 0;
    while (rem >= NT_ - ti) { rem -= NT_ - ti; ti++; }
    const int tj = ti + rem;
    const int b  = blockIdx.z;
    const int m0 = ti * 128, n0 = tj * 128;

    const __half* Kt = g_kt + (size_t)b * HW_ * CK_;

    __shared__ float ps1[128][2];
    __shared__ float ps2[128][4];
    extern __shared__ __half smh[];

    float acc[2][8][4] = {};
    mma_mainloop_h(Kt + (size_t)m0 * CK_, Kt + (size_t)n0 * CK_,
                   CK_, CK_, 0, CK_, acc);

    const int tid  = threadIdx.x;
    const int lane = tid & 31;
    const int wid  = tid >> 5;
    const int warpM0 = (wid & 3) * 32;
    const int warpN0 = (wid >> 2) * 64;
    const int t4 = lane >> 2;
    const int tm = lane & 3;

    __half* S = g_sim + (size_t)b * HW_ * HW_;
    const float* rn = g_rn + (size_t)b * HW_;
    const float Gsq = __uint_as_float(g_gsq_bits[b]);
    const float SC = 0.0625f;

    float rs[2][2] = {};
    #pragma unroll
    for (int i = 0; i < 2; i++) {
        const int rl1 = warpM0 + i * 16 + t4;
        const int rl2 = rl1 + 8;
        const float u1 = sqrtf(rn[m0 + rl1] * Gsq) * SC;
        const float u2 = sqrtf(rn[m0 + rl2] * Gsq) * SC;
        #pragma unroll
        for (int j = 0; j < 8; j++) {
            const int cg = n0 + warpN0 + j * 8 + tm * 2;
            __half2 h1 = __floats2half2_rn(__expf(acc[i][j][0] * SC - u1),
                                           __expf(acc[i][j][1] * SC - u1));
            __half2 h2 = __floats2half2_rn(__expf(acc[i][j][2] * SC - u2),
                                           __expf(acc[i][j][3] * SC - u2));
            float2 f1 = __half22float2(h1);
            float2 f2 = __half22float2(h2);
            rs[i][0] += f1.x + f1.y;
            rs[i][1] += f2.x + f2.y;
            *(__half2*)&S[(size_t)(m0 + rl1) * HW_ + cg] = h1;
            *(__half2*)&S[(size_t)(m0 + rl2) * HW_ + cg] = h2;
        }
    }
    #pragma unroll
    for (int i = 0; i < 2; i++)
        #pragma unroll
        for (int r = 0; r < 2; r++) {
            rs[i][r] += __shfl_xor_sync(0xFFFFFFFFu, rs[i][r], 1);
            rs[i][r] += __shfl_xor_sync(0xFFFFFFFFu, rs[i][r], 2);
        }
    if (tm == 0) {
        #pragma unroll
        for (int i = 0; i < 2; i++) {
            ps1[warpM0 + i * 16 + t4][warpN0 >> 6]     = rs[i][0];
            ps1[warpM0 + i * 16 + t4 + 8][warpN0 >> 6] = rs[i][1];
        }
    }
    __syncthreads();
    if (tid < 128) {
        g_ps[((size_t)b * HW_ + m0 + tid) * NT_ + tj] = ps1[tid][0] + ps1[tid][1];
    }

    if (ti != tj) {
        cp_wait<0>();
        __syncthreads();
        float cs[8][2] = {};
        #pragma unroll
        for (int j = 0; j < 8; j++) {
            const int cl = warpN0 + j * 8 + tm * 2;
            const float uc0 = sqrtf(rn[n0 + cl] * Gsq) * SC;
            const float uc1 = sqrtf(rn[n0 + cl + 1] * Gsq) * SC;
            #pragma unroll
            for (int i = 0; i < 2; i++) {
                const int r1 = warpM0 + i * 16 + t4;
                const int r2 = r1 + 8;
                __half h0 = __float2half_rn(__expf(acc[i][j][0] * SC - uc0));
                __half h1 = __float2half_rn(__expf(acc[i][j][1] * SC - uc1));
                __half h2 = __float2half_rn(__expf(acc[i][j][2] * SC - uc0));
                __half h3 = __float2half_rn(__expf(acc[i][j][3] * SC - uc1));
                smh[cl * 136 + r1]       = h0;
                smh[(cl + 1) * 136 + r1] = h1;
                smh[cl * 136 + r2]       = h2;
                smh[(cl + 1) * 136 + r2] = h3;
                cs[j][0] += __half2float(h0) + __half2float(h2);
                cs[j][1] += __half2float(h1) + __half2float(h3);
            }
        }
        #pragma unroll
        for (int j = 0; j < 8; j++)
            #pragma unroll
            for (int c = 0; c < 2; c++) {
                cs[j][c] += __shfl_xor_sync(0xFFFFFFFFu, cs[j][c], 4);
                cs[j][c] += __shfl_xor_sync(0xFFFFFFFFu, cs[j][c], 8);
                cs[j][c] += __shfl_xor_sync(0xFFFFFFFFu, cs[j][c], 16);
            }
        if (t4 == 0) {
            #pragma unroll
            for (int j = 0; j < 8; j++) {
                ps2[warpN0 + j * 8 + tm * 2][wid & 3]     = cs[j][0];
                ps2[warpN0 + j * 8 + tm * 2 + 1][wid & 3] = cs[j][1];
            }
        }
        __syncthreads();
        if (tid < 128) {
            g_ps[((size_t)b * HW_ + n0 + tid) * NT_ + ti] =
                ps2[tid][0] + ps2[tid][1] + ps2[tid][2] + ps2[tid][3];
        }
        #pragma unroll
        for (int it = 0; it < 8; it++) {
            int row = (tid >> 4) + it * 16;
            int c8  = tid & 15;
            uint4 v = *(const uint4*)&smh[row * 136 + c8 * 8];
            *(uint4*)&S[(size_t)(n0 + row) * HW_ + m0 + c8 * 8] = v;
        }
    }
}

// ---------------------------------------------------------------------------
// ctx partial: grid (2, 50, 8)
// ---------------------------------------------------------------------------
__global__ void __launch_bounds__(256, 2) ctx_mma()
{
    const int b = blockIdx.z >> 2;
    const int sp = blockIdx.z & 3;
    const int n0 = blockIdx.x * 128;   // v-channel tile
    const int m0 = blockIdx.y * 128;   // pixel tile

    float acc[2][8][4] = {};
    mma_mainloop_h(g_sim + ((size_t)b * HW_ + m0) * HW_,
                   g_v + ((size_t)b * CV_ + n0) * HW_,
                   HW_, HW_, sp * KSPLIT, (sp + 1) * KSPLIT, acc);

    const int lane = threadIdx.x & 31;
    const int wid  = threadIdx.x >> 5;
    const int warpM0 = (wid & 3) * 32;
    const int warpN0 = (wid >> 2) * 64;
    const int t4 = lane >> 2;
    const int tm = lane & 3;

    float* Cp = g_ctxp + (size_t)(b * NSPLIT + sp) * HW_ * CV_;
    #pragma unroll
    for (int i = 0; i < 2; i++) {
        int r1 = m0 + warpM0 + i * 16 + t4;
        int r2 = r1 + 8;
        #pragma unroll
        for (int j = 0; j < 8; j++) {
            int cg = n0 + warpN0 + j * 8 + tm * 2;
            *(float2*)&Cp[(size_t)r1 * CV_ + cg] = make_float2(acc[i][j][0], acc[i][j][1]);
            *(float2*)&Cp[(size_t)r2 * CV_ + cg] = make_float2(acc[i][j][2], acc[i][j][3]);
        }
    }
}

// ---------------------------------------------------------------------------
// out: grid (50, 4, 2)
// ---------------------------------------------------------------------------
__global__ void __launch_bounds__(256, 2) out_mma(
    const float* __restrict__ bW, float* __restrict__ out)
{
    const int b = blockIdx.z;
    const int n0 = blockIdx.x * 128;
    const int m0 = blockIdx.y * 128;

    float acc[2][8][4] = {};
    mma_mainloop_h(g_wr + 2 * 131072 + (size_t)m0 * CV_,
                   g_ctx + ((size_t)b * HW_ + n0) * CV_,
                   CV_, CV_, 0, CV_, acc);

    const int lane = threadIdx.x & 31;
    const int wid  = threadIdx.x >> 5;
    const int warpM0 = (wid & 3) * 32;
    const int warpN0 = (wid >> 2) * 64;
    const int t4 = lane >> 2;
    const int tm = lane & 3;

    float* O = out + (size_t)b * CO_ * HW_;
    #pragma unroll
    for (int i = 0; i < 2; i++) {
        int r1 = m0 + warpM0 + i * 16 + t4;
        int r2 = r1 + 8;
        float b1 = bW[r1], b2 = bW[r2];
        #pragma unroll
        for (int j = 0; j < 8; j++) {
            int cg = n0 + warpN0 + j * 8 + tm * 2;
            *(float2*)&O[(size_t)r1 * HW_ + cg] =
                make_float2(acc[i][j][0] + b1, acc[i][j][1] + b1);
            *(float2*)&O[(size_t)r2 * HW_ + cg] =
                make_float2(acc[i][j][2] + b2, acc[i][j][3] + b2);
        }
    }
}

// ---------------------------------------------------------------------------
// Small kernels
// ---------------------------------------------------------------------------
// Row squared norms + per-batch max (deterministic atomicMax on float bits).
// grid (1600), 256 thr; rows b = row / HW_ handled by contiguous layout.
__global__ void __launch_bounds__(256) norm_kernel()
{
    __shared__ float wmax[8];
    const int w = threadIdx.x >> 5;
    const int lane = threadIdx.x & 31;
    const int row = blockIdx.x * 8 + w;
    const __half* p = g_kt + (size_t)row * CK_ + lane * 8;
    float s = 0.f;
    #pragma unroll
    for (int i = 0; i < 4; i++) {
        float2 f = __half22float2(*(const __half2*)(p + i * 2));
        s += f.x * f.x + f.y * f.y;
    }
    #pragma unroll
    for (int d = 16; d > 0; d >>= 1) s += __shfl_xor_sync(0xFFFFFFFFu, s, d);
    if (lane == 0) {
        g_rn[row] = s;
        wmax[w] = s;
    }
    __syncthreads();
    if (threadIdx.x == 0) {
        float m = wmax[0];
        #pragma unroll
        for (int i = 1; i < 8; i++) m = fmaxf(m, wmax[i]);
        // all 8 rows of this block belong to one batch (HW_ % 8 == 0)
        const int b = row / HW_;
        atomicMax(&g_gsq_bits[b], __float_as_uint(m));   // s >= 0 -> bit-monotone
    }
}

__global__ void __launch_bounds__(256) rowinv_kernel()
{
    const int r = blockIdx.x * 256 + threadIdx.x;
    const float* p = g_ps + (size_t)r * NT_;
    float s = 0.f;
    #pragma unroll
    for (int j = 0; j < NT_; j++) s += p[j];
    g_inv[r] = 1.f / s;
}

__global__ void __launch_bounds__(256) reduce_ctx()
{
    const size_t f = (size_t)blockIdx.x * 256 + threadIdx.x;
    const size_t per_b = (size_t)HW_ * CV_;
    const size_t g = f * 4;
    const size_t b = g / per_b;
    const size_t e = g % per_b;
    const size_t n = e / CV_;
    const float inv = g_inv[b * HW_ + n];
    const float4 a = *(const float4*)&g_ctxp[(b * NSPLIT + 0) * per_b + e];
    const float4 c = *(const float4*)&g_ctxp[(b * NSPLIT + 1) * per_b + e];
    const float4 d = *(const float4*)&g_ctxp[(b * NSPLIT + 2) * per_b + e];
    const float4 h = *(const float4*)&g_ctxp[(b * NSPLIT + 3) * per_b + e];
    __half2* dst = (__half2*)&g_ctx[b * per_b + e];
    dst[0] = __floats2half2_rn((a.x + c.x + d.x + h.x) * inv,
                               (a.y + c.y + d.y + h.y) * inv);
    dst[1] = __floats2half2_rn((a.z + c.z + d.z + h.z) * inv,
                               (a.w + c.w + d.w + h.w) * inv);
}

// ---------------------------------------------------------------------------
// Launch
// ---------------------------------------------------------------------------
extern "C" void kernel_launch(void* const* d_in, const int* in_sizes, int n_in,
                              void* d_out, int out_size)
{
    const float* x     = (const float*)d_in[0];
    const float* wk    = (const float*)d_in[1];
    const float* bk    = (const float*)d_in[2];
    const float* gamma = (const float*)d_in[3];
    const float* beta  = (const float*)d_in[4];
    const float* rmean = (const float*)d_in[5];
    const float* rvar  = (const float*)d_in[6];
    const float* wv    = (const float*)d_in[7];
    const float* bv    = (const float*)d_in[8];
    const float* wW    = (const float*)d_in[9];
    const float* bW    = (const float*)d_in[10];
    float* out = (float*)d_out;

    cudaFuncSetAttribute(kv_mma,  cudaFuncAttributeMaxDynamicSharedMemorySize, SMEM_DYN);
    cudaFuncSetAttribute(sim_sym, cudaFuncAttributeMaxDynamicSharedMemorySize, SMEM_DYN);
    cudaFuncSetAttribute(ctx_mma, cudaFuncAttributeMaxDynamicSharedMemorySize, SMEM_DYN);
    cudaFuncSetAttribute(out_mma, cudaFuncAttributeMaxDynamicSharedMemorySize, SMEM_DYN);

    // reset per-batch max accumulator (graph-capturable memset node)
    void* gsq_addr = nullptr;
    cudaGetSymbolAddress(&gsq_addr, g_gsq_bits);
    cudaMemsetAsync(gsq_addr, 0, sizeof(unsigned) * B_);

    dim3 blk(256);
    round_w<<<dim3(1536, 1, 1), blk>>>(wk, wv, wW);
    transpose_x<<<dim3(200, 16, 2), dim3(32, 8)>>>(x);
    kv_mma<<<dim3(50, 2, 4), blk, SMEM_DYN>>>(bk, gamma, beta, rmean, rvar, bv);
    norm_kernel<<<dim3(1600, 1, 1), blk>>>();
    sim_sym<<<dim3(1275, 1, 2), blk, SMEM_DYN>>>();
    rowinv_kernel<<<dim3(50, 1, 1), blk>>>();
    ctx_mma<<<dim3(2, 50, 2 * NSPLIT), blk, SMEM_DYN>>>();
    reduce_ctx<<<dim3(3200, 1, 1), blk>>>();
    out_mma<<<dim3(50, 4, 2), blk, SMEM_DYN>>>(bW, out);
}

// round 13
// speedup vs baseline: 1.5382x; 1.5382x over previous
#include <cuda_runtime.h>
#include <cuda_fp16.h>
#include <math.h>
#include <stdint.h>

#define BN_EPS 1e-5f

// Problem constants
#define B_   2
#define C_   512
#define HW_  6400
#define CK_  256
#define CV_  256
#define CO_  512
#define NSPLIT 4
#define KSPLIT (HW_ / NSPLIT)   // 1600
#define NT_  50                 // 6400 / 128 tiles per dim

#define NSTAGE 4
#define KCH   32                          // k-halfs per chunk
#define SROW  40                          // halfs per smem row (32 + 8 pad)
#define STAGE_H (2 * 128 * SROW)          // halfs per stage (A+B)
#define SMEM_DYN (NSTAGE * STAGE_H * 2)   // 81920 bytes

// ---------------------------------------------------------------------------
// Scratch (device globals)
// ---------------------------------------------------------------------------
__device__ __align__(16) __half g_xt [(size_t)B_ * HW_ * C_];   // x^T: [b][n][c]
__device__ __align__(16) __half g_wr [3 * 131072];              // wk | wv | wW (half)
__device__ __align__(16) __half g_kt [(size_t)B_ * HW_ * CK_];  // K^T: [pixel][channel]
__device__ __align__(16) __half g_v  [(size_t)B_ * CV_ * HW_];  // V: [vchan][pixel]
__device__ __align__(16) __half g_sim[(size_t)B_ * HW_ * HW_];  // exp(S - u_row)
__device__ __align__(16) __half g_ctx[(size_t)B_ * HW_ * CV_];  // ctx^T: [n][v] normalized
__device__ float g_ctxp[(size_t)B_ * NSPLIT * HW_ * CV_];       // ctx partials (fp32)
__device__ float g_rn  [(size_t)B_ * HW_];                      // ||k_r||^2 (stored-half K)
__device__ float g_gsq [B_];                                    // max_r ||k_r||^2
__device__ float g_ps  [(size_t)B_ * HW_ * NT_];                // row-sum partials
__device__ float g_inv [(size_t)B_ * HW_];                      // 1/rowsum

// ---------------------------------------------------------------------------
// Helpers
// ---------------------------------------------------------------------------
__device__ __forceinline__ void mma_f16(float* c, const uint32_t* a, const uint32_t* b) {
    asm volatile(
        "mma.sync.aligned.m16n8k16.row.col.f32.f16.f16.f32 "
        "{%0,%1,%2,%3}, {%4,%5,%6,%7}, {%8,%9}, {%0,%1,%2,%3};"
        : "+f"(c[0]), "+f"(c[1]), "+f"(c[2]), "+f"(c[3])
        : "r"(a[0]), "r"(a[1]), "r"(a[2]), "r"(a[3]), "r"(b[0]), "r"(b[1]));
}

__device__ __forceinline__ void ldm4(uint32_t& r0, uint32_t& r1, uint32_t& r2,
                                     uint32_t& r3, uint32_t addr) {
    asm volatile("ldmatrix.sync.aligned.m8n8.x4.shared.b16 {%0,%1,%2,%3}, [%4];"
                 : "=r"(r0), "=r"(r1), "=r"(r2), "=r"(r3) : "r"(addr));
}

__device__ __forceinline__ void cp16(uint32_t saddr, const void* g) {
    asm volatile("cp.async.cg.shared.global [%0], [%1], 16;" :: "r"(saddr), "l"(g));
}
__device__ __forceinline__ void cp_commit() {
    asm volatile("cp.async.commit_group;");
}
template<int N> __device__ __forceinline__ void cp_wait() {
    asm volatile("cp.async.wait_group %0;" :: "n"(N));
}

// ---------------------------------------------------------------------------
// Pipelined FP16 mainloop: acc += sum_{k in [kb,ke)} A[m][k]*B[n][k]
// 128x128 tile, 8 warps, 4-stage cp.async, ldmatrix fragment loads.
// Requires (ke-kb)/KCH >= 3.
// ---------------------------------------------------------------------------
__device__ __forceinline__ void mma_mainloop_h(
    const __half* __restrict__ A, const __half* __restrict__ B,
    int lda, int ldb, int kb, int ke, float acc[2][8][4])
{
    extern __shared__ __half smh[];
    const int tid  = threadIdx.x;
    const int lane = tid & 31;
    const int wid  = tid >> 5;
    const int warpM0 = (wid & 3) * 32;
    const int warpN0 = (wid >> 2) * 64;

    const int lr   = tid >> 1;
    const int hseg = (tid & 1) * 16;

    const __half* Ar = A + (size_t)lr * lda + kb + hseg;
    const __half* Br = B + (size_t)lr * ldb + kb + hseg;

    const uint32_t sbase = (uint32_t)__cvta_generic_to_shared(smh);

    // per-lane ldmatrix byte offsets within a stage
    uint32_t a_off[2][2], b_off[2][4];
    {
        const int ra = warpM0 + (lane & 15);
        const int ca = (lane >> 4) * 8;
        #pragma unroll
        for (int i = 0; i < 2; i++)
            #pragma unroll
            for (int s = 0; s < 2; s++)
                a_off[i][s] = (uint32_t)(((ra + i * 16) * SROW + s * 16 + ca) * 2);
        const int jj = lane >> 4;             // extra j within the x4
        const int cb = ((lane >> 3) & 1) * 8;
        #pragma unroll
        for (int jp = 0; jp < 4; jp++)
            #pragma unroll
            for (int s = 0; s < 2; s++)
                b_off[s][jp] = (uint32_t)((128 * SROW +
                    (warpN0 + (jp * 2 + jj) * 8 + (lane & 7)) * SROW + s * 16 + cb) * 2);
    }

    const int ktiles = (ke - kb) / KCH;

#define ISSUE_TILE(stage, kof) do {                                  \
        uint32_t so_ = sbase + (stage) * (STAGE_H * 2);              \
        uint32_t sa_ = so_ + (lr * SROW + hseg) * 2;                 \
        uint32_t sb_ = sa_ + 128 * SROW * 2;                         \
        cp16(sa_,      Ar + (kof));                                  \
        cp16(sa_ + 16, Ar + (kof) + 8);                              \
        cp16(sb_,      Br + (kof));                                  \
        cp16(sb_ + 16, Br + (kof) + 8);                              \
    } while (0)

    ISSUE_TILE(0, 0);       cp_commit();
    ISSUE_TILE(1, KCH);     cp_commit();
    ISSUE_TILE(2, 2 * KCH); cp_commit();

    for (int t = 0; t < ktiles; t++) {
        cp_wait<2>();
        __syncthreads();
        if (t + 3 < ktiles) ISSUE_TILE((t + 3) & 3, (t + 3) * KCH);
        cp_commit();

        const uint32_t so = sbase + (t & 3) * (STAGE_H * 2);
        #pragma unroll
        for (int s = 0; s < 2; s++) {
            uint32_t a[2][4], b[8][2];
            ldm4(a[0][0], a[0][1], a[0][2], a[0][3], so + a_off[0][s]);
            ldm4(a[1][0], a[1][1], a[1][2], a[1][3], so + a_off[1][s]);
            ldm4(b[0][0], b[0][1], b[1][0], b[1][1], so + b_off[s][0]);
            ldm4(b[2][0], b[2][1], b[3][0], b[3][1], so + b_off[s][1]);
            ldm4(b[4][0], b[4][1], b[5][0], b[5][1], so + b_off[s][2]);
            ldm4(b[6][0], b[6][1], b[7][0], b[7][1], so + b_off[s][3]);
            #pragma unroll
            for (int i = 0; i < 2; i++)
                #pragma unroll
                for (int j = 0; j < 8; j++)
                    mma_f16(acc[i][j], a[i], b[j]);
        }
    }
#undef ISSUE_TILE
}

// ---------------------------------------------------------------------------
// Transpose + halve x: [b][c][n] -> g_xt [b][n][c].  grid (200,16,2), 32x8
// ---------------------------------------------------------------------------
__global__ void __launch_bounds__(256) transpose_x(const float* __restrict__ x)
{
    __shared__ float t[32][33];
    const int n0 = blockIdx.x * 32;
    const int c0 = blockIdx.y * 32;
    const int b  = blockIdx.z;
    const int tx = threadIdx.x, ty = threadIdx.y;

    #pragma unroll
    for (int j = 0; j < 4; j++) {
        int c = c0 + ty + j * 8;
        t[ty + j * 8][tx] = x[((size_t)b * C_ + c) * HW_ + n0 + tx];
    }
    __syncthreads();
    #pragma unroll
    for (int j = 0; j < 4; j++) {
        int n = n0 + ty + j * 8;
        g_xt[((size_t)b * HW_ + n) * C_ + c0 + tx] = __float2half_rn(t[tx][ty + j * 8]);
    }
}

// Halve weight matrices.  grid (1536), 256 thr
__global__ void __launch_bounds__(256) round_w(
    const float* __restrict__ wk, const float* __restrict__ wv,
    const float* __restrict__ wW)
{
    const int i = blockIdx.x * 256 + threadIdx.x;
    const float* src = (i < 131072) ? (wk + i)
                     : (i < 262144) ? (wv + i - 131072)
                                    : (wW + i - 262144);
    g_wr[i] = __float2half_rn(*src);
}

// ---------------------------------------------------------------------------
// kv via mma.  grid (50, 2, 4)  z = b*2 + isV
// ---------------------------------------------------------------------------
__global__ void __launch_bounds__(256, 2) kv_mma(
    const float* __restrict__ bk,
    const float* __restrict__ gamma, const float* __restrict__ beta,
    const float* __restrict__ rmean, const float* __restrict__ rvar,
    const float* __restrict__ bv)
{
    const int n0 = blockIdx.x * 128;
    const int m0 = blockIdx.y * 128;
    const int b  = blockIdx.z >> 1;
    const int isV = blockIdx.z & 1;

    const __half* A = g_wr + (size_t)isV * 131072 + (size_t)m0 * C_;
    const __half* B = g_xt + ((size_t)b * HW_ + n0) * C_;

    float acc[2][8][4] = {};
    mma_mainloop_h(A, B, C_, C_, 0, C_, acc);

    const int lane = threadIdx.x & 31;
    const int wid  = threadIdx.x >> 5;
    const int warpM0 = (wid & 3) * 32;
    const int warpN0 = (wid >> 2) * 64;
    const int t4 = lane >> 2;
    const int tm = lane & 3;

    if (isV) {
        __half* V = g_v + (size_t)b * CV_ * HW_;
        #pragma unroll
        for (int i = 0; i < 2; i++) {
            int r1 = m0 + warpM0 + i * 16 + t4;
            int r2 = r1 + 8;
            float b1 = bv[r1], b2 = bv[r2];
            #pragma unroll
            for (int j = 0; j < 8; j++) {
                int cg = n0 + warpN0 + j * 8 + tm * 2;
                *(__half2*)&V[(size_t)r1 * HW_ + cg] =
                    __floats2half2_rn(acc[i][j][0] + b1, acc[i][j][1] + b1);
                *(__half2*)&V[(size_t)r2 * HW_ + cg] =
                    __floats2half2_rn(acc[i][j][2] + b2, acc[i][j][3] + b2);
            }
        }
    } else {
        __half* kt = g_kt + (size_t)b * HW_ * CK_;
        #pragma unroll
        for (int i = 0; i < 2; i++) {
            int r1 = m0 + warpM0 + i * 16 + t4;
            int r2 = r1 + 8;
            float bb1 = bk[r1], bb2 = bk[r2];
            float sc1 = gamma[r1] / sqrtf(rvar[r1] + BN_EPS);
            float sc2 = gamma[r2] / sqrtf(rvar[r2] + BN_EPS);
            float mu1 = rmean[r1], mu2 = rmean[r2];
            float be1 = beta[r1],  be2 = beta[r2];
            #pragma unroll
            for (int j = 0; j < 8; j++) {
                int cg = n0 + warpN0 + j * 8 + tm * 2;
                float t0 = fmaxf((acc[i][j][0] + bb1 - mu1) * sc1 + be1, 0.f);
                float t1 = fmaxf((acc[i][j][1] + bb1 - mu1) * sc1 + be1, 0.f);
                float t2 = fmaxf((acc[i][j][2] + bb2 - mu2) * sc2 + be2, 0.f);
                float t3 = fmaxf((acc[i][j][3] + bb2 - mu2) * sc2 + be2, 0.f);
                kt[(size_t)cg * CK_ + r1]       = __float2half_rn(t0);
                kt[(size_t)(cg + 1) * CK_ + r1] = __float2half_rn(t1);
                kt[(size_t)cg * CK_ + r2]       = __float2half_rn(t2);
                kt[(size_t)(cg + 1) * CK_ + r2] = __float2half_rn(t3);
            }
        }
    }
}

// ---------------------------------------------------------------------------
// Symmetric sim: fused exp + partial sums, mirror staged via smem.
// grid (1275, 1, 2), 256 threads.
// ---------------------------------------------------------------------------
__global__ void __launch_bounds__(256, 2) sim_sym()
{
    int rem = blockIdx.x, ti = 0;
    while (rem >= NT_ - ti) { rem -= NT_ - ti; ti++; }
    const int tj = ti + rem;
    const int b  = blockIdx.z;
    const int m0 = ti * 128, n0 = tj * 128;

    const __half* Kt = g_kt + (size_t)b * HW_ * CK_;

    __shared__ float ps1[128][2];
    __shared__ float ps2[128][4];
    extern __shared__ __half smh[];

    float acc[2][8][4] = {};
    mma_mainloop_h(Kt + (size_t)m0 * CK_, Kt + (size_t)n0 * CK_,
                   CK_, CK_, 0, CK_, acc);

    const int tid  = threadIdx.x;
    const int lane = tid & 31;
    const int wid  = tid >> 5;
    const int warpM0 = (wid & 3) * 32;
    const int warpN0 = (wid >> 2) * 64;
    const int t4 = lane >> 2;
    const int tm = lane & 3;

    __half* S = g_sim + (size_t)b * HW_ * HW_;
    const float* rn = g_rn + (size_t)b * HW_;
    const float Gsq = g_gsq[b];
    const float SC = 0.0625f;

    // primary tile: rounded-half store + row-sum partials (of rounded values)
    float rs[2][2] = {};
    #pragma unroll
    for (int i = 0; i < 2; i++) {
        const int rl1 = warpM0 + i * 16 + t4;
        const int rl2 = rl1 + 8;
        const float u1 = sqrtf(rn[m0 + rl1] * Gsq) * SC;
        const float u2 = sqrtf(rn[m0 + rl2] * Gsq) * SC;
        #pragma unroll
        for (int j = 0; j < 8; j++) {
            const int cg = n0 + warpN0 + j * 8 + tm * 2;
            __half2 h1 = __floats2half2_rn(__expf(acc[i][j][0] * SC - u1),
                                           __expf(acc[i][j][1] * SC - u1));
            __half2 h2 = __floats2half2_rn(__expf(acc[i][j][2] * SC - u2),
                                           __expf(acc[i][j][3] * SC - u2));
            float2 f1 = __half22float2(h1);
            float2 f2 = __half22float2(h2);
            rs[i][0] += f1.x + f1.y;
            rs[i][1] += f2.x + f2.y;
            *(__half2*)&S[(size_t)(m0 + rl1) * HW_ + cg] = h1;
            *(__half2*)&S[(size_t)(m0 + rl2) * HW_ + cg] = h2;
        }
    }
    #pragma unroll
    for (int i = 0; i < 2; i++)
        #pragma unroll
        for (int r = 0; r < 2; r++) {
            rs[i][r] += __shfl_xor_sync(0xFFFFFFFFu, rs[i][r], 1);
            rs[i][r] += __shfl_xor_sync(0xFFFFFFFFu, rs[i][r], 2);
        }
    if (tm == 0) {
        #pragma unroll
        for (int i = 0; i < 2; i++) {
            ps1[warpM0 + i * 16 + t4][warpN0 >> 6]     = rs[i][0];
            ps1[warpM0 + i * 16 + t4 + 8][warpN0 >> 6] = rs[i][1];
        }
    }
    __syncthreads();
    if (tid < 128) {
        g_ps[((size_t)b * HW_ + m0 + tid) * NT_ + tj] = ps1[tid][0] + ps1[tid][1];
    }

    // mirror tile: exp with column's own bound; stage transposed in smem
    if (ti != tj) {
        cp_wait<0>();
        __syncthreads();          // pipeline buffers now free for reuse
        float cs[8][2] = {};
        #pragma unroll
        for (int j = 0; j < 8; j++) {
            const int cl = warpN0 + j * 8 + tm * 2;
            const float uc0 = sqrtf(rn[n0 + cl] * Gsq) * SC;
            const float uc1 = sqrtf(rn[n0 + cl + 1] * Gsq) * SC;
            #pragma unroll
            for (int i = 0; i < 2; i++) {
                const int r1 = warpM0 + i * 16 + t4;
                const int r2 = r1 + 8;
                __half h0 = __float2half_rn(__expf(acc[i][j][0] * SC - uc0));
                __half h1 = __float2half_rn(__expf(acc[i][j][1] * SC - uc1));
                __half h2 = __float2half_rn(__expf(acc[i][j][2] * SC - uc0));
                __half h3 = __float2half_rn(__expf(acc[i][j][3] * SC - uc1));
                smh[cl * 136 + r1]       = h0;
                smh[(cl + 1) * 136 + r1] = h1;
                smh[cl * 136 + r2]       = h2;
                smh[(cl + 1) * 136 + r2] = h3;
                cs[j][0] += __half2float(h0) + __half2float(h2);
                cs[j][1] += __half2float(h1) + __half2float(h3);
            }
        }
        #pragma unroll
        for (int j = 0; j < 8; j++)
            #pragma unroll
            for (int c = 0; c < 2; c++) {
                cs[j][c] += __shfl_xor_sync(0xFFFFFFFFu, cs[j][c], 4);
                cs[j][c] += __shfl_xor_sync(0xFFFFFFFFu, cs[j][c], 8);
                cs[j][c] += __shfl_xor_sync(0xFFFFFFFFu, cs[j][c], 16);
            }
        if (t4 == 0) {
            #pragma unroll
            for (int j = 0; j < 8; j++) {
                ps2[warpN0 + j * 8 + tm * 2][wid & 3]     = cs[j][0];
                ps2[warpN0 + j * 8 + tm * 2 + 1][wid & 3] = cs[j][1];
            }
        }
        __syncthreads();
        if (tid < 128) {
            g_ps[((size_t)b * HW_ + n0 + tid) * NT_ + ti] =
                ps2[tid][0] + ps2[tid][1] + ps2[tid][2] + ps2[tid][3];
        }
        // coalesced flush of mirror tile
        #pragma unroll
        for (int it = 0; it < 8; it++) {
            int row = (tid >> 4) + it * 16;
            int c8  = tid & 15;
            uint4 v = *(const uint4*)&smh[row * 136 + c8 * 8];
            *(uint4*)&S[(size_t)(n0 + row) * HW_ + m0 + c8 * 8] = v;
        }
    }
}

// ---------------------------------------------------------------------------
// ctx partial: grid (2, 50, 8)
// ---------------------------------------------------------------------------
__global__ void __launch_bounds__(256, 2) ctx_mma()
{
    const int b = blockIdx.z >> 2;
    const int sp = blockIdx.z & 3;
    const int n0 = blockIdx.x * 128;   // v-channel tile
    const int m0 = blockIdx.y * 128;   // pixel tile

    float acc[2][8][4] = {};
    mma_mainloop_h(g_sim + ((size_t)b * HW_ + m0) * HW_,
                   g_v + ((size_t)b * CV_ + n0) * HW_,
                   HW_, HW_, sp * KSPLIT, (sp + 1) * KSPLIT, acc);

    const int lane = threadIdx.x & 31;
    const int wid  = threadIdx.x >> 5;
    const int warpM0 = (wid & 3) * 32;
    const int warpN0 = (wid >> 2) * 64;
    const int t4 = lane >> 2;
    const int tm = lane & 3;

    float* Cp = g_ctxp + (size_t)(b * NSPLIT + sp) * HW_ * CV_;
    #pragma unroll
    for (int i = 0; i < 2; i++) {
        int r1 = m0 + warpM0 + i * 16 + t4;
        int r2 = r1 + 8;
        #pragma unroll
        for (int j = 0; j < 8; j++) {
            int cg = n0 + warpN0 + j * 8 + tm * 2;
            *(float2*)&Cp[(size_t)r1 * CV_ + cg] = make_float2(acc[i][j][0], acc[i][j][1]);
            *(float2*)&Cp[(size_t)r2 * CV_ + cg] = make_float2(acc[i][j][2], acc[i][j][3]);
        }
    }
}

// ---------------------------------------------------------------------------
// out: grid (50, 4, 2)
// ---------------------------------------------------------------------------
__global__ void __launch_bounds__(256, 2) out_mma(
    const float* __restrict__ bW, float* __restrict__ out)
{
    const int b = blockIdx.z;
    const int n0 = blockIdx.x * 128;
    const int m0 = blockIdx.y * 128;

    float acc[2][8][4] = {};
    mma_mainloop_h(g_wr + 2 * 131072 + (size_t)m0 * CV_,
                   g_ctx + ((size_t)b * HW_ + n0) * CV_,
                   CV_, CV_, 0, CV_, acc);

    const int lane = threadIdx.x & 31;
    const int wid  = threadIdx.x >> 5;
    const int warpM0 = (wid & 3) * 32;
    const int warpN0 = (wid >> 2) * 64;
    const int t4 = lane >> 2;
    const int tm = lane & 3;

    float* O = out + (size_t)b * CO_ * HW_;
    #pragma unroll
    for (int i = 0; i < 2; i++) {
        int r1 = m0 + warpM0 + i * 16 + t4;
        int r2 = r1 + 8;
        float b1 = bW[r1], b2 = bW[r2];
        #pragma unroll
        for (int j = 0; j < 8; j++) {
            int cg = n0 + warpN0 + j * 8 + tm * 2;
            *(float2*)&O[(size_t)r1 * HW_ + cg] =
                make_float2(acc[i][j][0] + b1, acc[i][j][1] + b1);
            *(float2*)&O[(size_t)r2 * HW_ + cg] =
                make_float2(acc[i][j][2] + b2, acc[i][j][3] + b2);
        }
    }
}

// ---------------------------------------------------------------------------
// Small kernels
// ---------------------------------------------------------------------------
__global__ void __launch_bounds__(256) norm_kernel()
{
    const int w = threadIdx.x >> 5;
    const int lane = threadIdx.x & 31;
    const int row = blockIdx.x * 8 + w;
    const __half* p = g_kt + (size_t)row * CK_ + lane * 8;
    float s = 0.f;
    #pragma unroll
    for (int i = 0; i < 4; i++) {
        float2 f = __half22float2(*(const __half2*)(p + i * 2));
        s += f.x * f.x + f.y * f.y;
    }
    #pragma unroll
    for (int d = 16; d > 0; d >>= 1) s += __shfl_xor_sync(0xFFFFFFFFu, s, d);
    if (lane == 0) g_rn[row] = s;
}

__global__ void __launch_bounds__(256) gmax_kernel()
{
    const int b = blockIdx.x;
    const int tid = threadIdx.x;
    __shared__ float red[256];
    float m = 0.f;
    for (int i = tid; i < HW_; i += 256) m = fmaxf(m, g_rn[(size_t)b * HW_ + i]);
    red[tid] = m;
    __syncthreads();
    for (int s = 128; s > 0; s >>= 1) {
        if (tid < s) red[tid] = fmaxf(red[tid], red[tid + s]);
        __syncthreads();
    }
    if (tid == 0) g_gsq[b] = red[0];
}

__global__ void __launch_bounds__(256) rowinv_kernel()
{
    const int r = blockIdx.x * 256 + threadIdx.x;
    const float* p = g_ps + (size_t)r * NT_;
    float s = 0.f;
    #pragma unroll
    for (int j = 0; j < NT_; j++) s += p[j];
    g_inv[r] = 1.f / s;
}

__global__ void __launch_bounds__(256) reduce_ctx()
{
    const size_t f = (size_t)blockIdx.x * 256 + threadIdx.x;
    const size_t per_b = (size_t)HW_ * CV_;
    const size_t g = f * 4;
    const size_t b = g / per_b;
    const size_t e = g % per_b;
    const size_t n = e / CV_;
    const float inv = g_inv[b * HW_ + n];
    const float4 a = *(const float4*)&g_ctxp[(b * NSPLIT + 0) * per_b + e];
    const float4 c = *(const float4*)&g_ctxp[(b * NSPLIT + 1) * per_b + e];
    const float4 d = *(const float4*)&g_ctxp[(b * NSPLIT + 2) * per_b + e];
    const float4 h = *(const float4*)&g_ctxp[(b * NSPLIT + 3) * per_b + e];
    __half2* dst = (__half2*)&g_ctx[b * per_b + e];
    dst[0] = __floats2half2_rn((a.x + c.x + d.x + h.x) * inv,
                               (a.y + c.y + d.y + h.y) * inv);
    dst[1] = __floats2half2_rn((a.z + c.z + d.z + h.z) * inv,
                               (a.w + c.w + d.w + h.w) * inv);
}

// ---------------------------------------------------------------------------
// Launch
// ---------------------------------------------------------------------------
extern "C" void kernel_launch(void* const* d_in, const int* in_sizes, int n_in,
                              void* d_out, int out_size)
{
    const float* x     = (const float*)d_in[0];
    const float* wk    = (const float*)d_in[1];
    const float* bk    = (const float*)d_in[2];
    const float* gamma = (const float*)d_in[3];
    const float* beta  = (const float*)d_in[4];
    const float* rmean = (const float*)d_in[5];
    const float* rvar  = (const float*)d_in[6];
    const float* wv    = (const float*)d_in[7];
    const float* bv    = (const float*)d_in[8];
    const float* wW    = (const float*)d_in[9];
    const float* bW    = (const float*)d_in[10];
    float* out = (float*)d_out;

    cudaFuncSetAttribute(kv_mma,  cudaFuncAttributeMaxDynamicSharedMemorySize, SMEM_DYN);
    cudaFuncSetAttribute(sim_sym, cudaFuncAttributeMaxDynamicSharedMemorySize, SMEM_DYN);
    cudaFuncSetAttribute(ctx_mma, cudaFuncAttributeMaxDynamicSharedMemorySize, SMEM_DYN);
    cudaFuncSetAttribute(out_mma, cudaFuncAttributeMaxDynamicSharedMemorySize, SMEM_DYN);

    dim3 blk(256);
    round_w<<<dim3(1536, 1, 1), blk>>>(wk, wv, wW);
    transpose_x<<<dim3(200, 16, 2), dim3(32, 8)>>>(x);
    kv_mma<<<dim3(50, 2, 4), blk, SMEM_DYN>>>(bk, gamma, beta, rmean, rvar, bv);
    norm_kernel<<<dim3(1600, 1, 1), blk>>>();
    gmax_kernel<<<dim3(2, 1, 1), blk>>>();
    sim_sym<<<dim3(1275, 1, 2), blk, SMEM_DYN>>>();
    rowinv_kernel<<<dim3(50, 1, 1), blk>>>();
    ctx_mma<<<dim3(2, 50, 2 * NSPLIT), blk, SMEM_DYN>>>();
    reduce_ctx<<<dim3(3200, 1, 1), blk>>>();
    out_mma<<<dim3(50, 4, 2), blk, SMEM_DYN>>>(bW, out);
}

// round 14
// speedup vs baseline: 1.5544x; 1.0106x over previous
#include <cuda_runtime.h>
#include <cuda_fp16.h>
#include <math.h>
#include <stdint.h>

#define BN_EPS 1e-5f

// Problem constants
#define B_   2
#define C_   512
#define HW_  6400
#define CK_  256
#define CV_  256
#define CO_  512
#define NSPLIT 4
#define KSPLIT (HW_ / NSPLIT)   // 1600
#define NT_  50                 // 6400 / 128 tiles per dim

#define NSTAGE 5
#define KCH   32                          // k-halfs per chunk
#define SROW  40                          // halfs per smem row (32 + 8 pad)
#define STAGE_H (2 * 128 * SROW)          // halfs per stage (A+B)
#define SMEM_DYN (NSTAGE * STAGE_H * 2)   // 102400 bytes

// ---------------------------------------------------------------------------
// Scratch (device globals)
// ---------------------------------------------------------------------------
__device__ __align__(16) __half g_xt [(size_t)B_ * HW_ * C_];   // x^T: [b][n][c]
__device__ __align__(16) __half g_wr [3 * 131072];              // wk | wv | wW (half)
__device__ __align__(16) __half g_kt [(size_t)B_ * HW_ * CK_];  // K^T: [pixel][channel]
__device__ __align__(16) __half g_v  [(size_t)B_ * CV_ * HW_];  // V: [vchan][pixel]
__device__ __align__(16) __half g_sim[(size_t)B_ * HW_ * HW_];  // exp(S - u_row)
__device__ __align__(16) __half g_ctx[(size_t)B_ * HW_ * CV_];  // ctx^T: [n][v] normalized
__device__ float g_ctxp[(size_t)B_ * NSPLIT * HW_ * CV_];       // ctx partials (fp32)
__device__ float g_rn  [(size_t)B_ * HW_];                      // ||k_r||^2 (stored-half K)
__device__ float g_gsq [B_];                                    // max_r ||k_r||^2
__device__ float g_ps  [(size_t)B_ * HW_ * NT_];                // row-sum partials
__device__ float g_inv [(size_t)B_ * HW_];                      // 1/rowsum

// ---------------------------------------------------------------------------
// Helpers
// ---------------------------------------------------------------------------
__device__ __forceinline__ void mma_f16(float* c, const uint32_t* a, const uint32_t* b) {
    asm volatile(
        "mma.sync.aligned.m16n8k16.row.col.f32.f16.f16.f32 "
        "{%0,%1,%2,%3}, {%4,%5,%6,%7}, {%8,%9}, {%0,%1,%2,%3};"
        : "+f"(c[0]), "+f"(c[1]), "+f"(c[2]), "+f"(c[3])
        : "r"(a[0]), "r"(a[1]), "r"(a[2]), "r"(a[3]), "r"(b[0]), "r"(b[1]));
}

__device__ __forceinline__ void ldm4(uint32_t& r0, uint32_t& r1, uint32_t& r2,
                                     uint32_t& r3, uint32_t addr) {
    asm volatile("ldmatrix.sync.aligned.m8n8.x4.shared.b16 {%0,%1,%2,%3}, [%4];"
                 : "=r"(r0), "=r"(r1), "=r"(r2), "=r"(r3) : "r"(addr));
}

__device__ __forceinline__ void cp16(uint32_t saddr, const void* g) {
    asm volatile("cp.async.cg.shared.global [%0], [%1], 16;" :: "r"(saddr), "l"(g));
}
__device__ __forceinline__ void cp_commit() {
    asm volatile("cp.async.commit_group;");
}
template<int N> __device__ __forceinline__ void cp_wait() {
    asm volatile("cp.async.wait_group %0;" :: "n"(N));
}

// ---------------------------------------------------------------------------
// Pipelined FP16 mainloop: acc += sum_{k in [kb,ke)} A[m][k]*B[n][k]
// 128x128 tile, 8 warps, 5-stage cp.async, ldmatrix fragment loads.
// Requires (ke-kb)/KCH >= 4.
// ---------------------------------------------------------------------------
__device__ __forceinline__ void mma_mainloop_h(
    const __half* __restrict__ A, const __half* __restrict__ B,
    int lda, int ldb, int kb, int ke, float acc[2][8][4])
{
    extern __shared__ __half smh[];
    const int tid  = threadIdx.x;
    const int lane = tid & 31;
    const int wid  = tid >> 5;
    const int warpM0 = (wid & 3) * 32;
    const int warpN0 = (wid >> 2) * 64;

    const int lr   = tid >> 1;
    const int hseg = (tid & 1) * 16;

    const __half* Ar = A + (size_t)lr * lda + kb + hseg;
    const __half* Br = B + (size_t)lr * ldb + kb + hseg;

    const uint32_t sbase = (uint32_t)__cvta_generic_to_shared(smh);

    // per-lane ldmatrix byte offsets within a stage
    uint32_t a_off[2][2], b_off[2][4];
    {
        const int ra = warpM0 + (lane & 15);
        const int ca = (lane >> 4) * 8;
        #pragma unroll
        for (int i = 0; i < 2; i++)
            #pragma unroll
            for (int s = 0; s < 2; s++)
                a_off[i][s] = (uint32_t)(((ra + i * 16) * SROW + s * 16 + ca) * 2);
        const int jj = lane >> 4;             // extra j within the x4
        const int cb = ((lane >> 3) & 1) * 8;
        #pragma unroll
        for (int jp = 0; jp < 4; jp++)
            #pragma unroll
            for (int s = 0; s < 2; s++)
                b_off[s][jp] = (uint32_t)((128 * SROW +
                    (warpN0 + (jp * 2 + jj) * 8 + (lane & 7)) * SROW + s * 16 + cb) * 2);
    }

    const int ktiles = (ke - kb) / KCH;

#define ISSUE_TILE(stage, kof) do {                                  \
        uint32_t so_ = sbase + (stage) * (STAGE_H * 2);              \
        uint32_t sa_ = so_ + (lr * SROW + hseg) * 2;                 \
        uint32_t sb_ = sa_ + 128 * SROW * 2;                         \
        cp16(sa_,      Ar + (kof));                                  \
        cp16(sa_ + 16, Ar + (kof) + 8);                              \
        cp16(sb_,      Br + (kof));                                  \
        cp16(sb_ + 16, Br + (kof) + 8);                              \
    } while (0)

    ISSUE_TILE(0, 0);       cp_commit();
    ISSUE_TILE(1, KCH);     cp_commit();
    ISSUE_TILE(2, 2 * KCH); cp_commit();
    ISSUE_TILE(3, 3 * KCH); cp_commit();

    int cur = 0;      // stage being consumed
    int nxt = 4;      // stage to fill next
    for (int t = 0; t < ktiles; t++) {
        cp_wait<3>();
        __syncthreads();
        if (t + 4 < ktiles) {
            ISSUE_TILE(nxt, (t + 4) * KCH);
            if (++nxt == NSTAGE) nxt = 0;
        }
        cp_commit();

        const uint32_t so = sbase + cur * (STAGE_H * 2);
        #pragma unroll
        for (int s = 0; s < 2; s++) {
            uint32_t a[2][4], b[8][2];
            ldm4(a[0][0], a[0][1], a[0][2], a[0][3], so + a_off[0][s]);
            ldm4(a[1][0], a[1][1], a[1][2], a[1][3], so + a_off[1][s]);
            ldm4(b[0][0], b[0][1], b[1][0], b[1][1], so + b_off[s][0]);
            ldm4(b[2][0], b[2][1], b[3][0], b[3][1], so + b_off[s][1]);
            ldm4(b[4][0], b[4][1], b[5][0], b[5][1], so + b_off[s][2]);
            ldm4(b[6][0], b[6][1], b[7][0], b[7][1], so + b_off[s][3]);
            #pragma unroll
            for (int i = 0; i < 2; i++)
                #pragma unroll
                for (int j = 0; j < 8; j++)
                    mma_f16(acc[i][j], a[i], b[j]);
        }
        if (++cur == NSTAGE) cur = 0;
    }
#undef ISSUE_TILE
}

// ---------------------------------------------------------------------------
// Transpose + halve x: [b][c][n] -> g_xt [b][n][c].  grid (200,16,2), 32x8
// ---------------------------------------------------------------------------
__global__ void __launch_bounds__(256) transpose_x(const float* __restrict__ x)
{
    __shared__ float t[32][33];
    const int n0 = blockIdx.x * 32;
    const int c0 = blockIdx.y * 32;
    const int b  = blockIdx.z;
    const int tx = threadIdx.x, ty = threadIdx.y;

    #pragma unroll
    for (int j = 0; j < 4; j++) {
        int c = c0 + ty + j * 8;
        t[ty + j * 8][tx] = x[((size_t)b * C_ + c) * HW_ + n0 + tx];
    }
    __syncthreads();
    #pragma unroll
    for (int j = 0; j < 4; j++) {
        int n = n0 + ty + j * 8;
        g_xt[((size_t)b * HW_ + n) * C_ + c0 + tx] = __float2half_rn(t[tx][ty + j * 8]);
    }
}

// Halve weight matrices.  grid (1536), 256 thr
__global__ void __launch_bounds__(256) round_w(
    const float* __restrict__ wk, const float* __restrict__ wv,
    const float* __restrict__ wW)
{
    const int i = blockIdx.x * 256 + threadIdx.x;
    const float* src = (i < 131072) ? (wk + i)
                     : (i < 262144) ? (wv + i - 131072)
                                    : (wW + i - 262144);
    g_wr[i] = __float2half_rn(*src);
}

// ---------------------------------------------------------------------------
// kv via mma.  grid (50, 2, 4)  z = b*2 + isV
// ---------------------------------------------------------------------------
__global__ void __launch_bounds__(256, 2) kv_mma(
    const float* __restrict__ bk,
    const float* __restrict__ gamma, const float* __restrict__ beta,
    const float* __restrict__ rmean, const float* __restrict__ rvar,
    const float* __restrict__ bv)
{
    const int n0 = blockIdx.x * 128;
    const int m0 = blockIdx.y * 128;
    const int b  = blockIdx.z >> 1;
    const int isV = blockIdx.z & 1;

    const __half* A = g_wr + (size_t)isV * 131072 + (size_t)m0 * C_;
    const __half* B = g_xt + ((size_t)b * HW_ + n0) * C_;

    float acc[2][8][4] = {};
    mma_mainloop_h(A, B, C_, C_, 0, C_, acc);

    const int lane = threadIdx.x & 31;
    const int wid  = threadIdx.x >> 5;
    const int warpM0 = (wid & 3) * 32;
    const int warpN0 = (wid >> 2) * 64;
    const int t4 = lane >> 2;
    const int tm = lane & 3;

    if (isV) {
        __half* V = g_v + (size_t)b * CV_ * HW_;
        #pragma unroll
        for (int i = 0; i < 2; i++) {
            int r1 = m0 + warpM0 + i * 16 + t4;
            int r2 = r1 + 8;
            float b1 = bv[r1], b2 = bv[r2];
            #pragma unroll
            for (int j = 0; j < 8; j++) {
                int cg = n0 + warpN0 + j * 8 + tm * 2;
                *(__half2*)&V[(size_t)r1 * HW_ + cg] =
                    __floats2half2_rn(acc[i][j][0] + b1, acc[i][j][1] + b1);
                *(__half2*)&V[(size_t)r2 * HW_ + cg] =
                    __floats2half2_rn(acc[i][j][2] + b2, acc[i][j][3] + b2);
            }
        }
    } else {
        __half* kt = g_kt + (size_t)b * HW_ * CK_;
        #pragma unroll
        for (int i = 0; i < 2; i++) {
            int r1 = m0 + warpM0 + i * 16 + t4;
            int r2 = r1 + 8;
            float bb1 = bk[r1], bb2 = bk[r2];
            float sc1 = gamma[r1] / sqrtf(rvar[r1] + BN_EPS);
            float sc2 = gamma[r2] / sqrtf(rvar[r2] + BN_EPS);
            float mu1 = rmean[r1], mu2 = rmean[r2];
            float be1 = beta[r1],  be2 = beta[r2];
            #pragma unroll
            for (int j = 0; j < 8; j++) {
                int cg = n0 + warpN0 + j * 8 + tm * 2;
                float t0 = fmaxf((acc[i][j][0] + bb1 - mu1) * sc1 + be1, 0.f);
                float t1 = fmaxf((acc[i][j][1] + bb1 - mu1) * sc1 + be1, 0.f);
                float t2 = fmaxf((acc[i][j][2] + bb2 - mu2) * sc2 + be2, 0.f);
                float t3 = fmaxf((acc[i][j][3] + bb2 - mu2) * sc2 + be2, 0.f);
                kt[(size_t)cg * CK_ + r1]       = __float2half_rn(t0);
                kt[(size_t)(cg + 1) * CK_ + r1] = __float2half_rn(t1);
                kt[(size_t)cg * CK_ + r2]       = __float2half_rn(t2);
                kt[(size_t)(cg + 1) * CK_ + r2] = __float2half_rn(t3);
            }
        }
    }
}

// ---------------------------------------------------------------------------
// Symmetric sim: fused exp + partial sums, mirror staged via smem.
// grid (1275, 1, 2), 256 threads.
// ---------------------------------------------------------------------------
__global__ void __launch_bounds__(256, 2) sim_sym()
{
    int rem = blockIdx.x, ti = 0;
    while (rem >= NT_ - ti) { rem -= NT_ - ti; ti++; }
    const int tj = ti + rem;
    const int b  = blockIdx.z;
    const int m0 = ti * 128, n0 = tj * 128;

    const __half* Kt = g_kt + (size_t)b * HW_ * CK_;

    __shared__ float ps1[128][2];
    __shared__ float ps2[128][4];
    extern __shared__ __half smh[];

    float acc[2][8][4] = {};
    mma_mainloop_h(Kt + (size_t)m0 * CK_, Kt + (size_t)n0 * CK_,
                   CK_, CK_, 0, CK_, acc);

    const int tid  = threadIdx.x;
    const int lane = tid & 31;
    const int wid  = tid >> 5;
    const int warpM0 = (wid & 3) * 32;
    const int warpN0 = (wid >> 2) * 64;
    const int t4 = lane >> 2;
    const int tm = lane & 3;

    __half* S = g_sim + (size_t)b * HW_ * HW_;
    const float* rn = g_rn + (size_t)b * HW_;
    const float Gsq = g_gsq[b];
    const float SC = 0.0625f;

    // primary tile: rounded-half store + row-sum partials (of rounded values)
    float rs[2][2] = {};
    #pragma unroll
    for (int i = 0; i < 2; i++) {
        const int rl1 = warpM0 + i * 16 + t4;
        const int rl2 = rl1 + 8;
        const float u1 = sqrtf(rn[m0 + rl1] * Gsq) * SC;
        const float u2 = sqrtf(rn[m0 + rl2] * Gsq) * SC;
        #pragma unroll
        for (int j = 0; j < 8; j++) {
            const int cg = n0 + warpN0 + j * 8 + tm * 2;
            __half2 h1 = __floats2half2_rn(__expf(acc[i][j][0] * SC - u1),
                                           __expf(acc[i][j][1] * SC - u1));
            __half2 h2 = __floats2half2_rn(__expf(acc[i][j][2] * SC - u2),
                                           __expf(acc[i][j][3] * SC - u2));
            float2 f1 = __half22float2(h1);
            float2 f2 = __half22float2(h2);
            rs[i][0] += f1.x + f1.y;
            rs[i][1] += f2.x + f2.y;
            *(__half2*)&S[(size_t)(m0 + rl1) * HW_ + cg] = h1;
            *(__half2*)&S[(size_t)(m0 + rl2) * HW_ + cg] = h2;
        }
    }
    #pragma unroll
    for (int i = 0; i < 2; i++)
        #pragma unroll
        for (int r = 0; r < 2; r++) {
            rs[i][r] += __shfl_xor_sync(0xFFFFFFFFu, rs[i][r], 1);
            rs[i][r] += __shfl_xor_sync(0xFFFFFFFFu, rs[i][r], 2);
        }
    if (tm == 0) {
        #pragma unroll
        for (int i = 0; i < 2; i++) {
            ps1[warpM0 + i * 16 + t4][warpN0 >> 6]     = rs[i][0];
            ps1[warpM0 + i * 16 + t4 + 8][warpN0 >> 6] = rs[i][1];
        }
    }
    __syncthreads();
    if (tid < 128) {
        g_ps[((size_t)b * HW_ + m0 + tid) * NT_ + tj] = ps1[tid][0] + ps1[tid][1];
    }

    // mirror tile: exp with column's own bound; stage transposed in smem
    if (ti != tj) {
        cp_wait<0>();
        __syncthreads();          // pipeline buffers now free for reuse
        float cs[8][2] = {};
        #pragma unroll
        for (int j = 0; j < 8; j++) {
            const int cl = warpN0 + j * 8 + tm * 2;
            const float uc0 = sqrtf(rn[n0 + cl] * Gsq) * SC;
            const float uc1 = sqrtf(rn[n0 + cl + 1] * Gsq) * SC;
            #pragma unroll
            for (int i = 0; i < 2; i++) {
                const int r1 = warpM0 + i * 16 + t4;
                const int r2 = r1 + 8;
                __half h0 = __float2half_rn(__expf(acc[i][j][0] * SC - uc0));
                __half h1 = __float2half_rn(__expf(acc[i][j][1] * SC - uc1));
                __half h2 = __float2half_rn(__expf(acc[i][j][2] * SC - uc0));
                __half h3 = __float2half_rn(__expf(acc[i][j][3] * SC - uc1));
                smh[cl * 136 + r1]       = h0;
                smh[(cl + 1) * 136 + r1] = h1;
                smh[cl * 136 + r2]       = h2;
                smh[(cl + 1) * 136 + r2] = h3;
                cs[j][0] += __half2float(h0) + __half2float(h2);
                cs[j][1] += __half2float(h1) + __half2float(h3);
            }
        }
        #pragma unroll
        for (int j = 0; j < 8; j++)
            #pragma unroll
            for (int c = 0; c < 2; c++) {
                cs[j][c] += __shfl_xor_sync(0xFFFFFFFFu, cs[j][c], 4);
                cs[j][c] += __shfl_xor_sync(0xFFFFFFFFu, cs[j][c], 8);
                cs[j][c] += __shfl_xor_sync(0xFFFFFFFFu, cs[j][c], 16);
            }
        if (t4 == 0) {
            #pragma unroll
            for (int j = 0; j < 8; j++) {
                ps2[warpN0 + j * 8 + tm * 2][wid & 3]     = cs[j][0];
                ps2[warpN0 + j * 8 + tm * 2 + 1][wid & 3] = cs[j][1];
            }
        }
        __syncthreads();
        if (tid < 128) {
            g_ps[((size_t)b * HW_ + n0 + tid) * NT_ + ti] =
                ps2[tid][0] + ps2[tid][1] + ps2[tid][2] + ps2[tid][3];
        }
        // coalesced flush of mirror tile
        #pragma unroll
        for (int it = 0; it < 8; it++) {
            int row = (tid >> 4) + it * 16;
            int c8  = tid & 15;
            uint4 v = *(const uint4*)&smh[row * 136 + c8 * 8];
            *(uint4*)&S[(size_t)(n0 + row) * HW_ + m0 + c8 * 8] = v;
        }
    }
}

// ---------------------------------------------------------------------------
// ctx partial: grid (2, 50, 8)
// ---------------------------------------------------------------------------
__global__ void __launch_bounds__(256, 2) ctx_mma()
{
    const int b = blockIdx.z >> 2;
    const int sp = blockIdx.z & 3;
    const int n0 = blockIdx.x * 128;   // v-channel tile
    const int m0 = blockIdx.y * 128;   // pixel tile

    float acc[2][8][4] = {};
    mma_mainloop_h(g_sim + ((size_t)b * HW_ + m0) * HW_,
                   g_v + ((size_t)b * CV_ + n0) * HW_,
                   HW_, HW_, sp * KSPLIT, (sp + 1) * KSPLIT, acc);

    const int lane = threadIdx.x & 31;
    const int wid  = threadIdx.x >> 5;
    const int warpM0 = (wid & 3) * 32;
    const int warpN0 = (wid >> 2) * 64;
    const int t4 = lane >> 2;
    const int tm = lane & 3;

    float* Cp = g_ctxp + (size_t)(b * NSPLIT + sp) * HW_ * CV_;
    #pragma unroll
    for (int i = 0; i < 2; i++) {
        int r1 = m0 + warpM0 + i * 16 + t4;
        int r2 = r1 + 8;
        #pragma unroll
        for (int j = 0; j < 8; j++) {
            int cg = n0 + warpN0 + j * 8 + tm * 2;
            *(float2*)&Cp[(size_t)r1 * CV_ + cg] = make_float2(acc[i][j][0], acc[i][j][1]);
            *(float2*)&Cp[(size_t)r2 * CV_ + cg] = make_float2(acc[i][j][2], acc[i][j][3]);
        }
    }
}

// ---------------------------------------------------------------------------
// out: grid (50, 4, 2)
// ---------------------------------------------------------------------------
__global__ void __launch_bounds__(256, 2) out_mma(
    const float* __restrict__ bW, float* __restrict__ out)
{
    const int b = blockIdx.z;
    const int n0 = blockIdx.x * 128;
    const int m0 = blockIdx.y * 128;

    float acc[2][8][4] = {};
    mma_mainloop_h(g_wr + 2 * 131072 + (size_t)m0 * CV_,
                   g_ctx + ((size_t)b * HW_ + n0) * CV_,
                   CV_, CV_, 0, CV_, acc);

    const int lane = threadIdx.x & 31;
    const int wid  = threadIdx.x >> 5;
    const int warpM0 = (wid & 3) * 32;
    const int warpN0 = (wid >> 2) * 64;
    const int t4 = lane >> 2;
    const int tm = lane & 3;

    float* O = out + (size_t)b * CO_ * HW_;
    #pragma unroll
    for (int i = 0; i < 2; i++) {
        int r1 = m0 + warpM0 + i * 16 + t4;
        int r2 = r1 + 8;
        float b1 = bW[r1], b2 = bW[r2];
        #pragma unroll
        for (int j = 0; j < 8; j++) {
            int cg = n0 + warpN0 + j * 8 + tm * 2;
            *(float2*)&O[(size_t)r1 * HW_ + cg] =
                make_float2(acc[i][j][0] + b1, acc[i][j][1] + b1);
            *(float2*)&O[(size_t)r2 * HW_ + cg] =
                make_float2(acc[i][j][2] + b2, acc[i][j][3] + b2);
        }
    }
}

// ---------------------------------------------------------------------------
// Small kernels
// ---------------------------------------------------------------------------
__global__ void __launch_bounds__(256) norm_kernel()
{
    const int w = threadIdx.x >> 5;
    const int lane = threadIdx.x & 31;
    const int row = blockIdx.x * 8 + w;
    const __half* p = g_kt + (size_t)row * CK_ + lane * 8;
    float s = 0.f;
    #pragma unroll
    for (int i = 0; i < 4; i++) {
        float2 f = __half22float2(*(const __half2*)(p + i * 2));
        s += f.x * f.x + f.y * f.y;
    }
    #pragma unroll
    for (int d = 16; d > 0; d >>= 1) s += __shfl_xor_sync(0xFFFFFFFFu, s, d);
    if (lane == 0) g_rn[row] = s;
}

__global__ void __launch_bounds__(256) gmax_kernel()
{
    const int b = blockIdx.x;
    const int tid = threadIdx.x;
    __shared__ float red[256];
    float m = 0.f;
    for (int i = tid; i < HW_; i += 256) m = fmaxf(m, g_rn[(size_t)b * HW_ + i]);
    red[tid] = m;
    __syncthreads();
    for (int s = 128; s > 0; s >>= 1) {
        if (tid < s) red[tid] = fmaxf(red[tid], red[tid + s]);
        __syncthreads();
    }
    if (tid == 0) g_gsq[b] = red[0];
}

__global__ void __launch_bounds__(256) rowinv_kernel()
{
    const int r = blockIdx.x * 256 + threadIdx.x;
    const float* p = g_ps + (size_t)r * NT_;
    float s = 0.f;
    #pragma unroll
    for (int j = 0; j < NT_; j++) s += p[j];
    g_inv[r] = 1.f / s;
}

__global__ void __launch_bounds__(256) reduce_ctx()
{
    const size_t f = (size_t)blockIdx.x * 256 + threadIdx.x;
    const size_t per_b = (size_t)HW_ * CV_;
    const size_t g = f * 4;
    const size_t b = g / per_b;
    const size_t e = g % per_b;
    const size_t n = e / CV_;
    const float inv = g_inv[b * HW_ + n];
    const float4 a = *(const float4*)&g_ctxp[(b * NSPLIT + 0) * per_b + e];
    const float4 c = *(const float4*)&g_ctxp[(b * NSPLIT + 1) * per_b + e];
    const float4 d = *(const float4*)&g_ctxp[(b * NSPLIT + 2) * per_b + e];
    const float4 h = *(const float4*)&g_ctxp[(b * NSPLIT + 3) * per_b + e];
    __half2* dst = (__half2*)&g_ctx[b * per_b + e];
    dst[0] = __floats2half2_rn((a.x + c.x + d.x + h.x) * inv,
                               (a.y + c.y + d.y + h.y) * inv);
    dst[1] = __floats2half2_rn((a.z + c.z + d.z + h.z) * inv,
                               (a.w + c.w + d.w + h.w) * inv);
}

// ---------------------------------------------------------------------------
// Launch
// ---------------------------------------------------------------------------
extern "C" void kernel_launch(void* const* d_in, const int* in_sizes, int n_in,
                              void* d_out, int out_size)
{
    const float* x     = (const float*)d_in[0];
    const float* wk    = (const float*)d_in[1];
    const float* bk    = (const float*)d_in[2];
    const float* gamma = (const float*)d_in[3];
    const float* beta  = (const float*)d_in[4];
    const float* rmean = (const float*)d_in[5];
    const float* rvar  = (const float*)d_in[6];
    const float* wv    = (const float*)d_in[7];
    const float* bv    = (const float*)d_in[8];
    const float* wW    = (const float*)d_in[9];
    const float* bW    = (const float*)d_in[10];
    float* out = (float*)d_out;

    cudaFuncSetAttribute(kv_mma,  cudaFuncAttributeMaxDynamicSharedMemorySize, SMEM_DYN);
    cudaFuncSetAttribute(sim_sym, cudaFuncAttributeMaxDynamicSharedMemorySize, SMEM_DYN);
    cudaFuncSetAttribute(ctx_mma, cudaFuncAttributeMaxDynamicSharedMemorySize, SMEM_DYN);
    cudaFuncSetAttribute(out_mma, cudaFuncAttributeMaxDynamicSharedMemorySize, SMEM_DYN);

    dim3 blk(256);
    round_w<<<dim3(1536, 1, 1), blk>>>(wk, wv, wW);
    transpose_x<<<dim3(200, 16, 2), dim3(32, 8)>>>(x);
    kv_mma<<<dim3(50, 2, 4), blk, SMEM_DYN>>>(bk, gamma, beta, rmean, rvar, bv);
    norm_kernel<<<dim3(1600, 1, 1), blk>>>();
    gmax_kernel<<<dim3(2, 1, 1), blk>>>();
    sim_sym<<<dim3(1275, 1, 2), blk, SMEM_DYN>>>();
    rowinv_kernel<<<dim3(50, 1, 1), blk>>>();
    ctx_mma<<<dim3(2, 50, 2 * NSPLIT), blk, SMEM_DYN>>>();
    reduce_ctx<<<dim3(3200, 1, 1), blk>>>();
    out_mma<<<dim3(50, 4, 2), blk, SMEM_DYN>>>(bW, out);
}